// round 4
// baseline (speedup 1.0000x reference)
#include <cuda_runtime.h>
#include <cstdint>

// ---------------------------------------------------------------------------
// LokrLinear: out = x @ (base_kernel + 2.0 * kron(lora_A@lora_B, O)) + bias
//
// Strategy (base-ISA only; tcgen05 is 'a'-gated and the harness builds
// compute_103 PTX):
//   1) WL = lora_A @ lora_B (16x16)
//   2) Wt[n][k] = round_tf32(base[k][n] + 2*WL[k/256][n/256]*O[k%256][n%256])
//   3) Xc = round_tf32(x)                       (unbiased RNA rounding: HW
//      HMMA-tf32 truncates, which would bias the K=4096 dot by ~1e-3)
//   4) out = Xc @ Wt^T + bias via mma.sync.m16n8k8.tf32, cp.async 4-stage
//      pipeline, SW128-swizzled smem, ldmatrix fragment loads.
// ---------------------------------------------------------------------------

static constexpr int MDIM = 16384;
static constexpr int KDIM = 4096;
static constexpr int NDIM = 4096;

static constexpr int BM = 128;
static constexpr int BN = 128;
static constexpr int BK = 32;                 // 32 tf32 = 128B row (SW128 atom)
static constexpr int STAGES = 4;
static constexpr int NKITER = KDIM / BK;      // 128
static constexpr int A_STAGE_BYTES = BM * BK * 4;   // 16384
static constexpr int B_STAGE_BYTES = BN * BK * 4;   // 16384
static constexpr int STAGE_BYTES = A_STAGE_BYTES + B_STAGE_BYTES; // 32768
static constexpr int SMEM_TOTAL = STAGES * STAGE_BYTES;           // 131072

// Device scratch (static __device__ arrays are the allowed scratch mechanism)
__device__ float g_WL[256];                           // (A@B) 16x16
__device__ float g_Wt[(size_t)NDIM * (size_t)KDIM];   // W_eff^T: [N][K], K contiguous
__device__ float g_Xc[(size_t)MDIM * (size_t)KDIM];   // tf32-rounded x

// ---------------------------------------------------------------------------
// Helpers
// ---------------------------------------------------------------------------
__device__ __forceinline__ uint32_t smem_u32(const void* p) {
    uint32_t a;
    asm("{ .reg .u64 t; cvta.to.shared.u64 t, %1; cvt.u32.u64 %0, t; }" : "=r"(a) : "l"(p));
    return a;
}

__device__ __forceinline__ float cvt_tf32(float x) {
    uint32_t o;
    asm("cvt.rna.tf32.f32 %0, %1;" : "=r"(o) : "f"(x));
    return __uint_as_float(o);
}

__device__ __forceinline__ void cp16(uint32_t saddr, const float* g) {
    asm volatile("cp.async.cg.shared.global [%0], [%1], 16;\n" :: "r"(saddr), "l"(g));
}
#define CP_COMMIT() asm volatile("cp.async.commit_group;\n" ::: "memory")

__device__ __forceinline__ void ldsm_x4(uint32_t& r0, uint32_t& r1, uint32_t& r2, uint32_t& r3,
                                        uint32_t addr) {
    asm volatile("ldmatrix.sync.aligned.m8n8.x4.shared.b16 {%0,%1,%2,%3}, [%4];\n"
                 : "=r"(r0), "=r"(r1), "=r"(r2), "=r"(r3) : "r"(addr));
}

__device__ __forceinline__ void mma_tf32(float& d0, float& d1, float& d2, float& d3,
                                         uint32_t a0, uint32_t a1, uint32_t a2, uint32_t a3,
                                         uint32_t b0, uint32_t b1) {
    asm volatile(
        "mma.sync.aligned.m16n8k8.row.col.f32.tf32.tf32.f32 "
        "{%0,%1,%2,%3}, {%4,%5,%6,%7}, {%8,%9}, {%0,%1,%2,%3};\n"
        : "+f"(d0), "+f"(d1), "+f"(d2), "+f"(d3)
        : "r"(a0), "r"(a1), "r"(a2), "r"(a3), "r"(b0), "r"(b1));
}

__device__ __forceinline__ uint32_t sw128(uint32_t off) {
    return off ^ ((off >> 3) & 0x70);
}

// ---------------------------------------------------------------------------
// Kernel 1: WL = lora_A @ lora_B (16x16)
// ---------------------------------------------------------------------------
__global__ void lokr_compute_wl(const float* __restrict__ A, const float* __restrict__ B) {
    const int i = threadIdx.x >> 4, j = threadIdx.x & 15;
    float s = 0.f;
#pragma unroll
    for (int r = 0; r < 16; r++) s += A[i * 16 + r] * B[r * 16 + j];
    g_WL[threadIdx.x] = s;
}

// ---------------------------------------------------------------------------
// Kernel 2: Wt[n][k] = round_tf32(base[k][n] + 2*WL[k/256][n/256]*O[k%256][n%256])
// (transpose through padded SMEM tiles; all global accesses coalesced)
// ---------------------------------------------------------------------------
__global__ void lokr_build_wt(const float* __restrict__ base, const float* __restrict__ O) {
    __shared__ float tb[32][33];
    __shared__ float to[32][33];
    const int k0 = blockIdx.x * 32;
    const int n0 = blockIdx.y * 32;
    const int tx = threadIdx.x, ty = threadIdx.y;
    const float wl2 = 2.0f * g_WL[(k0 >> 8) * 16 + (n0 >> 8)];
    const int p0 = k0 & 255, q0 = n0 & 255;
#pragma unroll
    for (int i = 0; i < 4; i++) {
        const int r = ty + i * 8;
        tb[r][tx] = base[(size_t)(k0 + r) * NDIM + n0 + tx];
        to[r][tx] = O[(p0 + r) * 256 + q0 + tx];
    }
    __syncthreads();
#pragma unroll
    for (int i = 0; i < 4; i++) {
        const int r = ty + i * 8;   // n-offset within tile
        g_Wt[(size_t)(n0 + r) * KDIM + k0 + tx] = cvt_tf32(tb[tx][r] + wl2 * to[tx][r]);
    }
}

// ---------------------------------------------------------------------------
// Kernel 3: Xc = round_tf32(x), vectorized
// ---------------------------------------------------------------------------
__global__ void lokr_cvt_x(const float4* __restrict__ x) {
    const size_t i = (size_t)blockIdx.x * blockDim.x + threadIdx.x;
    float4 v = x[i];
    v.x = cvt_tf32(v.x); v.y = cvt_tf32(v.y);
    v.z = cvt_tf32(v.z); v.w = cvt_tf32(v.w);
    reinterpret_cast<float4*>(g_Xc)[i] = v;
}

// ---------------------------------------------------------------------------
// Kernel 4: TF32 mma.sync GEMM. BM=128 x BN=128 x BK=32, 4-stage cp.async.
// 256 threads = 8 warps; warp grid 2(m) x 4(n); warp tile 64x32.
// SMEM: A[m][k] 128B rows SW128-swizzled; B[n][k] same.
// ---------------------------------------------------------------------------
__device__ __forceinline__ void gemm_fill_stage(uint32_t smem_base, int stage, int kt,
                                                const float* Abase, const float* Bbase,
                                                int tid) {
    const uint32_t sa = smem_base + stage * STAGE_BYTES;
    const uint32_t sb = sa + A_STAGE_BYTES;
    const int k0 = kt * BK;
    // A: 128 rows x 8 16B-chunks = 1024 chunks; 4 per thread
#pragma unroll
    for (int j = 0; j < 4; j++) {
        const int c = j * 256 + tid;
        const int row = c >> 3, col4 = c & 7;
        cp16(sa + sw128((uint32_t)(row * 128 + col4 * 16)),
             Abase + (size_t)row * KDIM + k0 + col4 * 4);
    }
    // B: same shape
#pragma unroll
    for (int j = 0; j < 4; j++) {
        const int c = j * 256 + tid;
        const int row = c >> 3, col4 = c & 7;
        cp16(sb + sw128((uint32_t)(row * 128 + col4 * 16)),
             Bbase + (size_t)row * KDIM + k0 + col4 * 4);
    }
    CP_COMMIT();
}

__global__ void __launch_bounds__(256, 1)
lokr_gemm_tf32(const float* __restrict__ bias, float* __restrict__ out) {
    extern __shared__ char smem[];
    const uint32_t smem_base = smem_u32(smem);
    const int tid = threadIdx.x;
    const int lane = tid & 31, wid = tid >> 5;
    const int warp_m = (wid & 1) * 64;   // 2 warps along m
    const int warp_n = (wid >> 1) * 32;  // 4 warps along n
    const int n0 = blockIdx.x * BN;
    const int m0 = blockIdx.y * BM;

    const float* Abase = g_Xc + (size_t)m0 * KDIM;
    const float* Bbase = g_Wt + (size_t)n0 * KDIM;

    // Per-thread ldmatrix byte offsets (before swizzle, before kk term).
    // x4 lane mapping: lanes 0-7 -> matrix0 rows, 8-15 -> m1, 16-23 -> m2, 24-31 -> m3.
    // Matrices per frag: (rows+0..7, k0..3), (rows+8..15, k0..3), (+0..7, k4..7), (+8..15, k4..7).
    uint32_t aOff[4], bOff[2];
    {
        const uint32_t colp = ((lane >> 4) & 1) * 16;  // k-half select (16B)
#pragma unroll
        for (int i = 0; i < 4; i++)
            aOff[i] = (uint32_t)((warp_m + i * 16 + (lane & 15)) * 128) + colp;
#pragma unroll
        for (int j = 0; j < 2; j++)
            bOff[j] = (uint32_t)((warp_n + j * 16 + (lane & 15)) * 128) + colp;
    }

    float d[4][4][4];
#pragma unroll
    for (int i = 0; i < 4; i++)
#pragma unroll
        for (int n = 0; n < 4; n++)
#pragma unroll
            for (int c = 0; c < 4; c++) d[i][n][c] = 0.f;

    // Prologue: fill STAGES-1 stages
#pragma unroll
    for (int s = 0; s < STAGES - 1; s++) gemm_fill_stage(smem_base, s, s, Abase, Bbase, tid);

    for (int kt = 0; kt < NKITER; kt++) {
        const int s = kt & (STAGES - 1);
        asm volatile("cp.async.wait_group %0;\n" :: "n"(STAGES - 2) : "memory");
        __syncthreads();

        // Refill the stage freed 1 iteration ago (writes overlap this compute)
        if (kt + STAGES - 1 < NKITER)
            gemm_fill_stage(smem_base, (kt + STAGES - 1) & (STAGES - 1), kt + STAGES - 1,
                            Abase, Bbase, tid);
        else
            CP_COMMIT();  // empty group keeps wait_group accounting uniform

        const uint32_t sa = smem_base + s * STAGE_BYTES;
        const uint32_t sb = sa + A_STAGE_BYTES;

#pragma unroll
        for (int kk = 0; kk < BK / 8; kk++) {
            const uint32_t kb = (uint32_t)(kk * 32);
            uint32_t a[4][4];
#pragma unroll
            for (int i = 0; i < 4; i++)
                ldsm_x4(a[i][0], a[i][1], a[i][2], a[i][3], sa + sw128(aOff[i] + kb));
            uint32_t b[4][2];
#pragma unroll
            for (int j = 0; j < 2; j++) {
                uint32_t r0, r1, r2, r3;
                ldsm_x4(r0, r1, r2, r3, sb + sw128(bOff[j] + kb));
                b[2 * j][0] = r0; b[2 * j + 1][0] = r1;
                b[2 * j][1] = r2; b[2 * j + 1][1] = r3;
            }
#pragma unroll
            for (int i = 0; i < 4; i++)
#pragma unroll
                for (int n = 0; n < 4; n++)
                    mma_tf32(d[i][n][0], d[i][n][1], d[i][n][2], d[i][n][3],
                             a[i][0], a[i][1], a[i][2], a[i][3], b[n][0], b[n][1]);
        }
    }

    // Epilogue: add bias, store float2 per (row, n-block)
#pragma unroll
    for (int i = 0; i < 4; i++) {
        const int row = m0 + warp_m + i * 16 + (lane >> 2);
#pragma unroll
        for (int n = 0; n < 4; n++) {
            const int col = n0 + warp_n + n * 8 + (lane & 3) * 2;
            const float bv0 = bias[col], bv1 = bias[col + 1];
            float2 v0 = make_float2(d[i][n][0] + bv0, d[i][n][1] + bv1);
            float2 v1 = make_float2(d[i][n][2] + bv0, d[i][n][3] + bv1);
            *reinterpret_cast<float2*>(out + (size_t)row * NDIM + col) = v0;
            *reinterpret_cast<float2*>(out + (size_t)(row + 8) * NDIM + col) = v1;
        }
    }
}

// ---------------------------------------------------------------------------
// Launch
// ---------------------------------------------------------------------------
extern "C" void kernel_launch(void* const* d_in, const int* in_sizes, int n_in,
                              void* d_out, int out_size) {
    (void)in_sizes; (void)n_in; (void)out_size;
    const float* x    = (const float*)d_in[0];
    const float* base = (const float*)d_in[1];
    const float* bias = (const float*)d_in[2];
    const float* la   = (const float*)d_in[3];
    const float* lb   = (const float*)d_in[4];
    const float* O    = (const float*)d_in[5];
    float* out = (float*)d_out;

    lokr_compute_wl<<<1, 256>>>(la, lb);

    dim3 gw(KDIM / 32, NDIM / 32);
    lokr_build_wt<<<gw, dim3(32, 8)>>>(base, O);

    const size_t n4 = (size_t)MDIM * KDIM / 4;   // 16M float4
    lokr_cvt_x<<<(unsigned)(n4 / 256), 256>>>((const float4*)x);

    cudaFuncSetAttribute(lokr_gemm_tf32, cudaFuncAttributeMaxDynamicSharedMemorySize, SMEM_TOTAL);
    dim3 gg(NDIM / BN, MDIM / BM);
    lokr_gemm_tf32<<<gg, 256, SMEM_TOTAL>>>(bias, out);
}

// round 5
// speedup vs baseline: 1.1850x; 1.1850x over previous
#include <cuda_runtime.h>
#include <cstdint>

// ---------------------------------------------------------------------------
// LokrLinear: out = x @ (base_kernel + 2.0 * kron(lora_A@lora_B, O)) + bias
//
// Base-ISA path (tcgen05 is 'a'-gated; harness builds compute_103 PTX):
//   1) WL = lora_A @ lora_B (16x16)
//   2) Wt[n][k] = round_tf32(base[k][n] + 2*WL[k/256][n/256]*O[k%256][n%256])
//   3) Xc = round_tf32(x)            (RNA rounding avoids HMMA truncation bias)
//   4) out = Xc @ Wt^T + bias via mma.sync.m16n8k8.tf32, cp.async 3-stage
//      pipeline, SW128-swizzled smem, ldmatrix fragment loads.
//
// R5 change: STAGES 4->3 (96KB smem) + __launch_bounds__(256,2) so two CTAs
// co-reside per SM; cross-CTA overlap hides the barrier/wait/ldmatrix bubbles
// that held the tensor pipe at 58%.
// ---------------------------------------------------------------------------

static constexpr int MDIM = 16384;
static constexpr int KDIM = 4096;
static constexpr int NDIM = 4096;

static constexpr int BM = 128;
static constexpr int BN = 128;
static constexpr int BK = 32;                 // 32 tf32 = 128B row (SW128 atom)
static constexpr int STAGES = 3;
static constexpr int NKITER = KDIM / BK;      // 128
static constexpr int A_STAGE_BYTES = BM * BK * 4;   // 16384
static constexpr int B_STAGE_BYTES = BN * BK * 4;   // 16384
static constexpr int STAGE_BYTES = A_STAGE_BYTES + B_STAGE_BYTES; // 32768
static constexpr int SMEM_TOTAL = STAGES * STAGE_BYTES;           // 98304

// Device scratch (static __device__ arrays are the allowed scratch mechanism)
__device__ float g_WL[256];                           // (A@B) 16x16
__device__ float g_Wt[(size_t)NDIM * (size_t)KDIM];   // W_eff^T: [N][K], K contiguous
__device__ float g_Xc[(size_t)MDIM * (size_t)KDIM];   // tf32-rounded x

// ---------------------------------------------------------------------------
// Helpers
// ---------------------------------------------------------------------------
__device__ __forceinline__ uint32_t smem_u32(const void* p) {
    uint32_t a;
    asm("{ .reg .u64 t; cvta.to.shared.u64 t, %1; cvt.u32.u64 %0, t; }" : "=r"(a) : "l"(p));
    return a;
}

__device__ __forceinline__ float cvt_tf32(float x) {
    uint32_t o;
    asm("cvt.rna.tf32.f32 %0, %1;" : "=r"(o) : "f"(x));
    return __uint_as_float(o);
}

__device__ __forceinline__ void cp16(uint32_t saddr, const float* g) {
    asm volatile("cp.async.cg.shared.global [%0], [%1], 16;\n" :: "r"(saddr), "l"(g));
}
#define CP_COMMIT() asm volatile("cp.async.commit_group;\n" ::: "memory")

__device__ __forceinline__ void ldsm_x4(uint32_t& r0, uint32_t& r1, uint32_t& r2, uint32_t& r3,
                                        uint32_t addr) {
    asm volatile("ldmatrix.sync.aligned.m8n8.x4.shared.b16 {%0,%1,%2,%3}, [%4];\n"
                 : "=r"(r0), "=r"(r1), "=r"(r2), "=r"(r3) : "r"(addr));
}

__device__ __forceinline__ void mma_tf32(float& d0, float& d1, float& d2, float& d3,
                                         uint32_t a0, uint32_t a1, uint32_t a2, uint32_t a3,
                                         uint32_t b0, uint32_t b1) {
    asm volatile(
        "mma.sync.aligned.m16n8k8.row.col.f32.tf32.tf32.f32 "
        "{%0,%1,%2,%3}, {%4,%5,%6,%7}, {%8,%9}, {%0,%1,%2,%3};\n"
        : "+f"(d0), "+f"(d1), "+f"(d2), "+f"(d3)
        : "r"(a0), "r"(a1), "r"(a2), "r"(a3), "r"(b0), "r"(b1));
}

__device__ __forceinline__ uint32_t sw128(uint32_t off) {
    return off ^ ((off >> 3) & 0x70);
}

// ---------------------------------------------------------------------------
// Kernel 1: WL = lora_A @ lora_B (16x16)
// ---------------------------------------------------------------------------
__global__ void lokr_compute_wl(const float* __restrict__ A, const float* __restrict__ B) {
    const int i = threadIdx.x >> 4, j = threadIdx.x & 15;
    float s = 0.f;
#pragma unroll
    for (int r = 0; r < 16; r++) s += A[i * 16 + r] * B[r * 16 + j];
    g_WL[threadIdx.x] = s;
}

// ---------------------------------------------------------------------------
// Kernel 2: Wt[n][k] = round_tf32(base[k][n] + 2*WL[k/256][n/256]*O[k%256][n%256])
// (transpose through padded SMEM tiles; all global accesses coalesced)
// ---------------------------------------------------------------------------
__global__ void lokr_build_wt(const float* __restrict__ base, const float* __restrict__ O) {
    __shared__ float tb[32][33];
    __shared__ float to[32][33];
    const int k0 = blockIdx.x * 32;
    const int n0 = blockIdx.y * 32;
    const int tx = threadIdx.x, ty = threadIdx.y;
    const float wl2 = 2.0f * g_WL[(k0 >> 8) * 16 + (n0 >> 8)];
    const int p0 = k0 & 255, q0 = n0 & 255;
#pragma unroll
    for (int i = 0; i < 4; i++) {
        const int r = ty + i * 8;
        tb[r][tx] = base[(size_t)(k0 + r) * NDIM + n0 + tx];
        to[r][tx] = O[(p0 + r) * 256 + q0 + tx];
    }
    __syncthreads();
#pragma unroll
    for (int i = 0; i < 4; i++) {
        const int r = ty + i * 8;   // n-offset within tile
        g_Wt[(size_t)(n0 + r) * KDIM + k0 + tx] = cvt_tf32(tb[tx][r] + wl2 * to[tx][r]);
    }
}

// ---------------------------------------------------------------------------
// Kernel 3: Xc = round_tf32(x), vectorized
// ---------------------------------------------------------------------------
__global__ void lokr_cvt_x(const float4* __restrict__ x) {
    const size_t i = (size_t)blockIdx.x * blockDim.x + threadIdx.x;
    float4 v = x[i];
    v.x = cvt_tf32(v.x); v.y = cvt_tf32(v.y);
    v.z = cvt_tf32(v.z); v.w = cvt_tf32(v.w);
    reinterpret_cast<float4*>(g_Xc)[i] = v;
}

// ---------------------------------------------------------------------------
// Kernel 4: TF32 mma.sync GEMM. BM=128 x BN=128 x BK=32, 3-stage cp.async,
// 2 CTAs/SM. 256 threads = 8 warps; warp grid 2(m) x 4(n); warp tile 64x32.
// SMEM: A[m][k] 128B rows SW128-swizzled; B[n][k] same.
// ---------------------------------------------------------------------------
__device__ __forceinline__ void gemm_fill_stage(uint32_t smem_base, int stage, int kt,
                                                const float* Abase, const float* Bbase,
                                                int tid) {
    const uint32_t sa = smem_base + stage * STAGE_BYTES;
    const uint32_t sb = sa + A_STAGE_BYTES;
    const int k0 = kt * BK;
    // A: 128 rows x 8 16B-chunks = 1024 chunks; 4 per thread
#pragma unroll
    for (int j = 0; j < 4; j++) {
        const int c = j * 256 + tid;
        const int row = c >> 3, col4 = c & 7;
        cp16(sa + sw128((uint32_t)(row * 128 + col4 * 16)),
             Abase + (size_t)row * KDIM + k0 + col4 * 4);
    }
    // B: same shape
#pragma unroll
    for (int j = 0; j < 4; j++) {
        const int c = j * 256 + tid;
        const int row = c >> 3, col4 = c & 7;
        cp16(sb + sw128((uint32_t)(row * 128 + col4 * 16)),
             Bbase + (size_t)row * KDIM + k0 + col4 * 4);
    }
    CP_COMMIT();
}

__global__ void __launch_bounds__(256, 2)
lokr_gemm_tf32(const float* __restrict__ bias, float* __restrict__ out) {
    extern __shared__ char smem[];
    const uint32_t smem_base = smem_u32(smem);
    const int tid = threadIdx.x;
    const int lane = tid & 31, wid = tid >> 5;
    const int warp_m = (wid & 1) * 64;   // 2 warps along m
    const int warp_n = (wid >> 1) * 32;  // 4 warps along n
    const int n0 = blockIdx.x * BN;
    const int m0 = blockIdx.y * BM;

    const float* Abase = g_Xc + (size_t)m0 * KDIM;
    const float* Bbase = g_Wt + (size_t)n0 * KDIM;

    // Per-thread ldmatrix byte offsets (before swizzle, before kk term).
    // x4 lane mapping: lanes 0-7 -> matrix0 rows, 8-15 -> m1, 16-23 -> m2, 24-31 -> m3.
    uint32_t aOff[4], bOff[2];
    {
        const uint32_t colp = ((lane >> 4) & 1) * 16;  // k-half select (16B)
#pragma unroll
        for (int i = 0; i < 4; i++)
            aOff[i] = (uint32_t)((warp_m + i * 16 + (lane & 15)) * 128) + colp;
#pragma unroll
        for (int j = 0; j < 2; j++)
            bOff[j] = (uint32_t)((warp_n + j * 16 + (lane & 15)) * 128) + colp;
    }

    float d[4][4][4];
#pragma unroll
    for (int i = 0; i < 4; i++)
#pragma unroll
        for (int n = 0; n < 4; n++)
#pragma unroll
            for (int c = 0; c < 4; c++) d[i][n][c] = 0.f;

    // Prologue: fill STAGES-1 stages
#pragma unroll
    for (int s = 0; s < STAGES - 1; s++) gemm_fill_stage(smem_base, s, s, Abase, Bbase, tid);

    for (int kt = 0; kt < NKITER; kt++) {
        const int s = kt % STAGES;
        asm volatile("cp.async.wait_group %0;\n" :: "n"(STAGES - 2) : "memory");
        __syncthreads();

        // Refill the stage freed 1 iteration ago (writes overlap this compute)
        if (kt + STAGES - 1 < NKITER)
            gemm_fill_stage(smem_base, (kt + STAGES - 1) % STAGES, kt + STAGES - 1,
                            Abase, Bbase, tid);
        else
            CP_COMMIT();  // empty group keeps wait_group accounting uniform

        const uint32_t sa = smem_base + s * STAGE_BYTES;
        const uint32_t sb = sa + A_STAGE_BYTES;

#pragma unroll
        for (int kk = 0; kk < BK / 8; kk++) {
            const uint32_t kb = (uint32_t)(kk * 32);
            uint32_t a[4][4];
#pragma unroll
            for (int i = 0; i < 4; i++)
                ldsm_x4(a[i][0], a[i][1], a[i][2], a[i][3], sa + sw128(aOff[i] + kb));
            uint32_t b[4][2];
#pragma unroll
            for (int j = 0; j < 2; j++) {
                uint32_t r0, r1, r2, r3;
                ldsm_x4(r0, r1, r2, r3, sb + sw128(bOff[j] + kb));
                b[2 * j][0] = r0; b[2 * j + 1][0] = r1;
                b[2 * j][1] = r2; b[2 * j + 1][1] = r3;
            }
#pragma unroll
            for (int i = 0; i < 4; i++)
#pragma unroll
                for (int n = 0; n < 4; n++)
                    mma_tf32(d[i][n][0], d[i][n][1], d[i][n][2], d[i][n][3],
                             a[i][0], a[i][1], a[i][2], a[i][3], b[n][0], b[n][1]);
        }
    }

    // Epilogue: add bias, store float2 per (row, n-block)
#pragma unroll
    for (int i = 0; i < 4; i++) {
        const int row = m0 + warp_m + i * 16 + (lane >> 2);
#pragma unroll
        for (int n = 0; n < 4; n++) {
            const int col = n0 + warp_n + n * 8 + (lane & 3) * 2;
            const float bv0 = bias[col], bv1 = bias[col + 1];
            float2 v0 = make_float2(d[i][n][0] + bv0, d[i][n][1] + bv1);
            float2 v1 = make_float2(d[i][n][2] + bv0, d[i][n][3] + bv1);
            *reinterpret_cast<float2*>(out + (size_t)row * NDIM + col) = v0;
            *reinterpret_cast<float2*>(out + (size_t)(row + 8) * NDIM + col) = v1;
        }
    }
}

// ---------------------------------------------------------------------------
// Launch
// ---------------------------------------------------------------------------
extern "C" void kernel_launch(void* const* d_in, const int* in_sizes, int n_in,
                              void* d_out, int out_size) {
    (void)in_sizes; (void)n_in; (void)out_size;
    const float* x    = (const float*)d_in[0];
    const float* base = (const float*)d_in[1];
    const float* bias = (const float*)d_in[2];
    const float* la   = (const float*)d_in[3];
    const float* lb   = (const float*)d_in[4];
    const float* O    = (const float*)d_in[5];
    float* out = (float*)d_out;

    lokr_compute_wl<<<1, 256>>>(la, lb);

    dim3 gw(KDIM / 32, NDIM / 32);
    lokr_build_wt<<<gw, dim3(32, 8)>>>(base, O);

    const size_t n4 = (size_t)MDIM * KDIM / 4;   // 16M float4
    lokr_cvt_x<<<(unsigned)(n4 / 256), 256>>>((const float4*)x);

    cudaFuncSetAttribute(lokr_gemm_tf32, cudaFuncAttributeMaxDynamicSharedMemorySize, SMEM_TOTAL);
    dim3 gg(NDIM / BN, MDIM / BM);
    lokr_gemm_tf32<<<gg, 256, SMEM_TOTAL>>>(bias, out);
}